// round 8
// baseline (speedup 1.0000x reference)
#include <cuda_runtime.h>
#include <cuda_fp16.h>
#include <math.h>
#include <stdint.h>

#define B_ROWS 16384
#define C_CLS  1000
#define F_DIM  256

#define BM 128
#define BN 128
#define KH_TAIL_K0 160         // fp16 tail k [160,176)
#define KF_BASE 176            // fp32 FFMA region k [176,256), 5 x 16
#define LDH 40                 // fp16 smem row stride (halves)
#define LDF 20                 // fp32 smem row stride (floats)

#define AH_OFF 0
#define BH_OFF 10240
#define AF_OFF 20480
#define BF_OFF 30720
#define BUF_BYTES 40960
#define PARAM_OFF (2 * BUF_BYTES)           // 81920
#define SMEM_BYTES (PARAM_OFF + 2048)       // 83968

// ---- device scratch ----
__device__ __half g_fh[(size_t)B_ROWS * F_DIM];
__device__ __half g_mh[(size_t)C_CLS * F_DIM];
__device__ float g_scores[(size_t)B_ROWS * C_CLS];
__device__ float g_f2[B_ROWS];
__device__ float g_m2[C_CLS];

__device__ __forceinline__ uint32_t smem_u32(const void* p) {
    uint32_t a;
    asm("{ .reg .u64 t; cvta.to.shared.u64 t, %1; cvt.u32.u64 %0, t; }" : "=r"(a) : "l"(p));
    return a;
}
__device__ __forceinline__ void cp16(uint32_t daddr, const void* src, uint32_t bytes) {
    asm volatile("cp.async.ca.shared.global [%0], [%1], 16, %2;"
                 :: "r"(daddr), "l"(src), "r"(bytes) : "memory");
}
__device__ __forceinline__ void mma_f16(float* d, const uint32_t* a, const uint32_t* b) {
    asm volatile(
        "mma.sync.aligned.m16n8k16.row.col.f32.f16.f16.f32 "
        "{%0,%1,%2,%3}, {%4,%5,%6,%7}, {%8,%9}, {%0,%1,%2,%3};"
        : "+f"(d[0]), "+f"(d[1]), "+f"(d[2]), "+f"(d[3])
        : "r"(a[0]), "r"(a[1]), "r"(a[2]), "r"(a[3]), "r"(b[0]), "r"(b[1]));
}

// -------------------------------------------------------------------------
// Convert fp32 -> fp16 and row sum-of-squares (fp32). One warp per row.
// -------------------------------------------------------------------------
__global__ void convert_kernel(const float* __restrict__ x,
                               __half* __restrict__ xh_out,
                               float* __restrict__ sq, int rows) {
    int warp = (blockIdx.x * blockDim.x + threadIdx.x) >> 5;
    int lane = threadIdx.x & 31;
    if (warp >= rows) return;
    const float* xr = x + (size_t)warp * F_DIM;
    float s = 0.f;
#pragma unroll
    for (int i = 0; i < 2; i++) {
        int e = (lane + i * 32) * 4;
        float4 v = *(const float4*)(xr + e);
        s += v.x * v.x + v.y * v.y + v.z * v.z + v.w * v.w;
        __half2 h0 = __floats2half2_rn(v.x, v.y);
        __half2 h1 = __floats2half2_rn(v.z, v.w);
        uint2 u;
        u.x = *(uint32_t*)&h0;
        u.y = *(uint32_t*)&h1;
        *(uint2*)(xh_out + (size_t)warp * F_DIM + e) = u;
    }
#pragma unroll
    for (int o = 16; o; o >>= 1) s += __shfl_xor_sync(0xffffffffu, s, o);
    if (lane == 0) sq[warp] = s;
}

// -------------------------------------------------------------------------
// Dual-pipe GEMM v2: fp16 HMMA on k [0,176) -> acc, fp32 FFMA on k [176,256)
// -> acc2 (separate regs, no cross-pipe RAW). Merge, then OpenMax epilogue.
// -------------------------------------------------------------------------
__global__ void __launch_bounds__(256)
gemm_openmax_dual(const float* __restrict__ featF,
                  const float* __restrict__ meanF,
                  const float* __restrict__ logits,
                  const float* __restrict__ wshape,
                  const float* __restrict__ wloc,
                  const float* __restrict__ wscale) {
    extern __shared__ char smem[];
    const uint32_t sb = smem_u32(smem);
    const int tid = threadIdx.x;
    const int lane = tid & 31;
    const int wid = tid >> 5;
    const int wm = wid & 1;
    const int wn = wid >> 1;
    const int rowBase = blockIdx.y * BM;
    const int colBase = blockIdx.x * BN;

    float* m2s  = (float*)(smem + PARAM_OFF);
    float* shs  = m2s + 128;
    float* lcs  = shs + 128;
    float* iscs = lcs + 128;
    if (tid < 128) {
        int gc = colBase + tid;
        int cc = (gc < C_CLS) ? gc : 0;
        m2s[tid] = g_m2[cc];
        shs[tid] = wshape[cc];
        lcs[tid] = wloc[cc];
        iscs[tid] = 1.f / wscale[cc];
    }

    float acc[4][4][4];    // HMMA accumulators
    float acc2[4][4][4];   // FFMA accumulators (independent)
#pragma unroll
    for (int i = 0; i < 4; i++)
#pragma unroll
        for (int j = 0; j < 4; j++)
#pragma unroll
            for (int q = 0; q < 4; q++) { acc[i][j][q] = 0.f; acc2[i][j][q] = 0.f; }

    // ---- loaders (one super-chunk: 32 fp16 k + 16 fp32 k) ----
    auto loadSuper = [&](int ch, int buf) {
        const uint32_t base = sb + (uint32_t)buf * BUF_BYTES;
        const int kh0 = ch * 32;
        const int kf0 = KF_BASE + ch * 16;
#pragma unroll
        for (int it2 = 0; it2 < 2; it2++) {
            int idx = tid + it2 * 256;
            int r = idx >> 2, q8 = (idx & 3) * 8;
            cp16(base + AH_OFF + (uint32_t)(r * LDH + q8) * 2,
                 g_fh + (size_t)(rowBase + r) * F_DIM + kh0 + q8, 16u);
        }
#pragma unroll
        for (int it2 = 0; it2 < 2; it2++) {
            int idx = tid + it2 * 256;
            int r = idx >> 2, q8 = (idx & 3) * 8;
            int gc = colBase + r;
            cp16(base + BH_OFF + (uint32_t)(r * LDH + q8) * 2,
                 g_mh + (size_t)((gc < C_CLS) ? gc : 0) * F_DIM + kh0 + q8,
                 (gc < C_CLS) ? 16u : 0u);
        }
#pragma unroll
        for (int it2 = 0; it2 < 2; it2++) {
            int idx = tid + it2 * 256;
            int r = idx >> 2, c4 = (idx & 3) * 4;
            cp16(base + AF_OFF + (uint32_t)(r * LDF + c4) * 4,
                 featF + (size_t)(rowBase + r) * F_DIM + kf0 + c4, 16u);
        }
#pragma unroll
        for (int it2 = 0; it2 < 2; it2++) {
            int idx = tid + it2 * 256;
            int r = idx >> 2, c4 = (idx & 3) * 4;
            int gc = colBase + r;
            cp16(base + BF_OFF + (uint32_t)(r * LDF + c4) * 4,
                 meanF + (size_t)((gc < C_CLS) ? gc : 0) * F_DIM + kf0 + c4,
                 (gc < C_CLS) ? 16u : 0u);
        }
        asm volatile("cp.async.commit_group;" ::: "memory");
    };
    auto loadTail = [&](int buf) {
        const uint32_t base = sb + (uint32_t)buf * BUF_BYTES;
        int r = tid >> 1, q8 = (tid & 1) * 8;
        cp16(base + AH_OFF + (uint32_t)(r * LDH + q8) * 2,
             g_fh + (size_t)(rowBase + r) * F_DIM + KH_TAIL_K0 + q8, 16u);
        int gc = colBase + r;
        cp16(base + BH_OFF + (uint32_t)(r * LDH + q8) * 2,
             g_mh + (size_t)((gc < C_CLS) ? gc : 0) * F_DIM + KH_TAIL_K0 + q8,
             (gc < C_CLS) ? 16u : 0u);
        asm volatile("cp.async.commit_group;" ::: "memory");
    };

    loadSuper(0, 0);

    const int g = lane >> 2;
    const int kq = lane & 3;
    const int lq = lane & 3;
    const int lr = lane >> 2;
    const int r0 = wm * 64 + g;
    const int c0 = wn * 32 + g;

#pragma unroll 1
    for (int it = 0; it < 5; it++) {
        if (it < 4) loadSuper(it + 1, (it + 1) & 1);
        else loadTail(1);
        asm volatile("cp.async.wait_group 1;" ::: "memory");
        __syncthreads();

        const char* bufp = smem + (it & 1) * BUF_BYTES;
        const __half* Ah = (const __half*)(bufp + AH_OFF);
        const __half* Bh = (const __half*)(bufp + BH_OFF);
        const float* Af = (const float*)(bufp + AF_OFF);
        const float* Bf = (const float*)(bufp + BF_OFF);

#pragma unroll
        for (int ks = 0; ks < 2; ks++) {
            // ---- HMMA stream (16 MMAs, fully independent of acc2) ----
            const int kb = ks * 16 + 2 * kq;
            uint32_t a[4][4], b[4][2];
#pragma unroll
            for (int ma = 0; ma < 4; ma++) {
                const __half* ap = Ah + (r0 + ma * 16) * LDH + kb;
                a[ma][0] = *(const uint32_t*)(ap);
                a[ma][1] = *(const uint32_t*)(ap + 8 * LDH);
                a[ma][2] = *(const uint32_t*)(ap + 8);
                a[ma][3] = *(const uint32_t*)(ap + 8 * LDH + 8);
            }
#pragma unroll
            for (int na = 0; na < 4; na++) {
                const __half* bp = Bh + (c0 + na * 8) * LDH + kb;
                b[na][0] = *(const uint32_t*)(bp);
                b[na][1] = *(const uint32_t*)(bp + 8);
            }
#pragma unroll
            for (int ma = 0; ma < 4; ma++)
#pragma unroll
                for (int na = 0; na < 4; na++)
                    mma_f16(acc[ma][na], a[ma], b[na]);

            // ---- FFMA stream: 4 k-pairs of the fp32 chunk -> acc2 ----
#pragma unroll
            for (int kp = 0; kp < 4; kp++) {
                const int kf = ks * 8 + kp * 2;
                float2 av[4][2], bv[4][2];
#pragma unroll
                for (int ma = 0; ma < 4; ma++) {
                    av[ma][0] = *(const float2*)(Af + (wm * 64 + ma * 16 + lr) * LDF + kf);
                    av[ma][1] = *(const float2*)(Af + (wm * 64 + ma * 16 + lr + 8) * LDF + kf);
                }
#pragma unroll
                for (int na = 0; na < 4; na++) {
                    bv[na][0] = *(const float2*)(Bf + (wn * 32 + na * 8 + 2 * lq) * LDF + kf);
                    bv[na][1] = *(const float2*)(Bf + (wn * 32 + na * 8 + 2 * lq + 1) * LDF + kf);
                }
#pragma unroll
                for (int ma = 0; ma < 4; ma++)
#pragma unroll
                    for (int na = 0; na < 4; na++)
#pragma unroll
                        for (int h = 0; h < 2; h++)
#pragma unroll
                            for (int q = 0; q < 2; q++) {
                                float t = fmaf(av[ma][h].x, bv[na][q].x,
                                               acc2[ma][na][h * 2 + q]);
                                acc2[ma][na][h * 2 + q] =
                                    fmaf(av[ma][h].y, bv[na][q].y, t);
                            }
            }
        }
        __syncthreads();
    }

    // ---- fp16 tail chunk: k [160,176) ----
    asm volatile("cp.async.wait_group 0;" ::: "memory");
    __syncthreads();
    {
        const char* bufp = smem + BUF_BYTES;
        const __half* Ah = (const __half*)(bufp + AH_OFF);
        const __half* Bh = (const __half*)(bufp + BH_OFF);
        const int kb = 2 * kq;
        uint32_t a[4][4], b[4][2];
#pragma unroll
        for (int ma = 0; ma < 4; ma++) {
            const __half* ap = Ah + (r0 + ma * 16) * LDH + kb;
            a[ma][0] = *(const uint32_t*)(ap);
            a[ma][1] = *(const uint32_t*)(ap + 8 * LDH);
            a[ma][2] = *(const uint32_t*)(ap + 8);
            a[ma][3] = *(const uint32_t*)(ap + 8 * LDH + 8);
        }
#pragma unroll
        for (int na = 0; na < 4; na++) {
            const __half* bp = Bh + (c0 + na * 8) * LDH + kb;
            b[na][0] = *(const uint32_t*)(bp);
            b[na][1] = *(const uint32_t*)(bp + 8);
        }
#pragma unroll
        for (int ma = 0; ma < 4; ma++)
#pragma unroll
            for (int na = 0; na < 4; na++)
                mma_f16(acc[ma][na], a[ma], b[na]);
    }

    // ---- merge + fused OpenMax epilogue ----
#pragma unroll
    for (int ma = 0; ma < 4; ma++) {
#pragma unroll
        for (int h = 0; h < 2; h++) {
            const int grow = rowBase + wm * 64 + ma * 16 + lr + h * 8;
            const float f2v = g_f2[grow];
            const float* lrow = logits + (size_t)grow * C_CLS;
            float* srow = g_scores + (size_t)grow * C_CLS;
#pragma unroll
            for (int na = 0; na < 4; na++) {
                const int col = wn * 32 + na * 8 + 2 * lq;
                const int gc = colBase + col;
                if (gc >= C_CLS) continue;
                float2 lg = *(const float2*)(lrow + gc);
                float dots[2] = { acc[ma][na][h * 2] + acc2[ma][na][h * 2],
                                  acc[ma][na][h * 2 + 1] + acc2[ma][na][h * 2 + 1] };
                float lgv[2] = { lg.x, lg.y };
                float res[2];
#pragma unroll
                for (int q = 0; q < 2; q++) {
                    const int c = col + q;
                    float d2 = f2v + m2s[c] - 2.f * dots[q];
                    float dist = sqrtf(fmaxf(d2, 1e-12f));
                    float xp = (dist - lcs[c]) * iscs[c];
                    float wv = 0.f;
                    if (xp > 0.f) {
                        float p = exp2f(shs[c] * __log2f(xp));
                        wv = 1.f - __expf(-p);
                    }
                    float w2 = wv * wv;
                    float w4 = w2 * w2;
                    float w10 = w4 * w4 * w2;
                    res[q] = lgv[q] * (1.f - w10);
                }
                float2 outp; outp.x = res[0]; outp.y = res[1];
                *(float2*)(srow + gc) = outp;
            }
        }
    }
}

// -------------------------------------------------------------------------
// Row softmax over C=1000: one 256-thread block per row.
// -------------------------------------------------------------------------
__global__ void __launch_bounds__(256)
softmax_kernel(const float* __restrict__ sc, float* __restrict__ out) {
    const int row = blockIdx.x;
    const float* rp = sc + (size_t)row * C_CLS;
    const int tid = threadIdx.x;

    float v[4];
    float m = -1e30f;
#pragma unroll
    for (int i = 0; i < 4; i++) {
        int idx = tid + i * 256;
        v[i] = (idx < C_CLS) ? rp[idx] : -1e30f;
        m = fmaxf(m, v[i]);
    }
#pragma unroll
    for (int o = 16; o; o >>= 1) m = fmaxf(m, __shfl_xor_sync(0xffffffffu, m, o));

    __shared__ float red[8];
    if ((tid & 31) == 0) red[tid >> 5] = m;
    __syncthreads();
    float bm = red[0];
#pragma unroll
    for (int ww = 1; ww < 8; ww++) bm = fmaxf(bm, red[ww]);
    __syncthreads();

    float e[4];
    float s = 0.f;
#pragma unroll
    for (int i = 0; i < 4; i++) {
        e[i] = __expf(v[i] - bm);
        s += e[i];
    }
#pragma unroll
    for (int o = 16; o; o >>= 1) s += __shfl_xor_sync(0xffffffffu, s, o);
    if ((tid & 31) == 0) red[tid >> 5] = s;
    __syncthreads();
    float total = 0.f;
#pragma unroll
    for (int ww = 0; ww < 8; ww++) total += red[ww];
    float inv = 1.f / total;

    float* orow = out + (size_t)row * C_CLS;
#pragma unroll
    for (int i = 0; i < 4; i++) {
        int idx = tid + i * 256;
        if (idx < C_CLS) orow[idx] = e[i] * inv;
    }
}

// -------------------------------------------------------------------------
extern "C" void kernel_launch(void* const* d_in, const int* in_sizes, int n_in,
                              void* d_out, int out_size) {
    const float* logits    = (const float*)d_in[0];
    const float* features  = (const float*)d_in[1];
    const float* mean_vecs = (const float*)d_in[2];
    const float* wb_shape  = (const float*)d_in[3];
    const float* wb_loc    = (const float*)d_in[4];
    const float* wb_scale  = (const float*)d_in[5];
    float* out = (float*)d_out;

    __half *fh, *mh;
    float *f2, *m2, *scores;
    cudaGetSymbolAddress((void**)&fh, g_fh);
    cudaGetSymbolAddress((void**)&mh, g_mh);
    cudaGetSymbolAddress((void**)&f2, g_f2);
    cudaGetSymbolAddress((void**)&m2, g_m2);
    cudaGetSymbolAddress((void**)&scores, g_scores);

    cudaFuncSetAttribute(gemm_openmax_dual,
                         cudaFuncAttributeMaxDynamicSharedMemorySize, SMEM_BYTES);

    convert_kernel<<<B_ROWS / 8, 256>>>(features, fh, f2, B_ROWS);
    convert_kernel<<<(C_CLS + 7) / 8, 256>>>(mean_vecs, mh, m2, C_CLS);

    dim3 grid((C_CLS + BN - 1) / BN, B_ROWS / BM);
    gemm_openmax_dual<<<grid, 256, SMEM_BYTES>>>(features, mean_vecs, logits,
                                                 wb_shape, wb_loc, wb_scale);

    softmax_kernel<<<B_ROWS, 256>>>(scores, out);
    (void)in_sizes; (void)n_in; (void)out_size;
}

// round 9
// speedup vs baseline: 1.3475x; 1.3475x over previous
#include <cuda_runtime.h>
#include <cuda_fp16.h>
#include <math.h>
#include <stdint.h>

#define B_ROWS 16384
#define C_CLS  1000
#define F_DIM  256

#define BM 16
#define LDA_H 264               // A smem row stride (halves)
#define LDB_H 40                // B smem row stride (halves)

// smem byte offsets
#define SC_OFF 0                        // scores: 16 x 1024 fp32 = 65536
#define PM_OFF 65536                    // m2     1024 f
#define PS_OFF (PM_OFF + 4096)          // shape
#define PL_OFF (PS_OFF + 4096)          // loc
#define PC_OFF (PL_OFF + 4096)          // scale
#define A_OFF  (PC_OFF + 4096)          // 81920: A 16 x 264 halves = 8448
#define B_OFF  (A_OFF + 8448)           // 90368: B 2 x (128 x 40 halves) = 20480
#define F2_OFF (B_OFF + 20480)          // 110848: 16 floats
#define SMEM_BYTES (F2_OFF + 64)        // 110912 -> 2 CTAs/SM

// ---- device scratch ----
__device__ __half g_fh[(size_t)B_ROWS * F_DIM];
__device__ __half g_mh[(size_t)C_CLS * F_DIM];
__device__ float g_f2[B_ROWS];
__device__ float g_m2[C_CLS];

__device__ __forceinline__ uint32_t smem_u32(const void* p) {
    uint32_t a;
    asm("{ .reg .u64 t; cvta.to.shared.u64 t, %1; cvt.u32.u64 %0, t; }" : "=r"(a) : "l"(p));
    return a;
}
__device__ __forceinline__ void cp16(uint32_t daddr, const void* src, uint32_t bytes) {
    asm volatile("cp.async.ca.shared.global [%0], [%1], 16, %2;"
                 :: "r"(daddr), "l"(src), "r"(bytes) : "memory");
}
__device__ __forceinline__ void mma_f16(float* d, const uint32_t* a, const uint32_t* b) {
    asm volatile(
        "mma.sync.aligned.m16n8k16.row.col.f32.f16.f16.f32 "
        "{%0,%1,%2,%3}, {%4,%5,%6,%7}, {%8,%9}, {%0,%1,%2,%3};"
        : "+f"(d[0]), "+f"(d[1]), "+f"(d[2]), "+f"(d[3])
        : "r"(a[0]), "r"(a[1]), "r"(a[2]), "r"(a[3]), "r"(b[0]), "r"(b[1]));
}

// -------------------------------------------------------------------------
// Convert fp32 -> fp16 and row sum-of-squares (fp32). One warp per row.
// -------------------------------------------------------------------------
__global__ void convert_kernel(const float* __restrict__ x,
                               __half* __restrict__ xh_out,
                               float* __restrict__ sq, int rows) {
    int warp = (blockIdx.x * blockDim.x + threadIdx.x) >> 5;
    int lane = threadIdx.x & 31;
    if (warp >= rows) return;
    const float* xr = x + (size_t)warp * F_DIM;
    float s = 0.f;
#pragma unroll
    for (int i = 0; i < 2; i++) {
        int e = (lane + i * 32) * 4;
        float4 v = *(const float4*)(xr + e);
        s += v.x * v.x + v.y * v.y + v.z * v.z + v.w * v.w;
        __half2 h0 = __floats2half2_rn(v.x, v.y);
        __half2 h1 = __floats2half2_rn(v.z, v.w);
        uint2 u;
        u.x = *(uint32_t*)&h0;
        u.y = *(uint32_t*)&h1;
        *(uint2*)(xh_out + (size_t)warp * F_DIM + e) = u;
    }
#pragma unroll
    for (int o = 16; o; o >>= 1) s += __shfl_xor_sync(0xffffffffu, s, o);
    if (lane == 0) sq[warp] = s;
}

// -------------------------------------------------------------------------
// Fused: fp16 mma.sync GEMM (16 rows x full C) + OpenMax + in-CTA softmax.
// 256 threads, 8 warps each own n=16 of a 128-col chunk; 8 chunks cover C.
// Scores live in smem only; output written directly.
// -------------------------------------------------------------------------
__global__ void __launch_bounds__(256, 2)
openmax_fused(const float* __restrict__ logits,
              const float* __restrict__ wshape,
              const float* __restrict__ wloc,
              const float* __restrict__ wscale,
              float* __restrict__ out) {
    extern __shared__ char smem[];
    const uint32_t sb = smem_u32(smem);
    const int tid = threadIdx.x;
    const int lane = tid & 31;
    const int wid = tid >> 5;
    const int rowBase = blockIdx.x * BM;

    float* scs  = (float*)(smem + SC_OFF);    // [16][1024]
    float* m2s  = (float*)(smem + PM_OFF);
    float* shs  = (float*)(smem + PS_OFF);
    float* lcs  = (float*)(smem + PL_OFF);
    float* wss  = (float*)(smem + PC_OFF);
    float* f2s  = (float*)(smem + F2_OFF);

    // ---- prologue loads: params (1000 floats x4), A tile (16 x 256 fp16) ----
    if (tid < 250) {
        cp16(sb + PM_OFF + tid * 16, g_m2   + tid * 4, 16u);
        cp16(sb + PS_OFF + tid * 16, wshape + tid * 4, 16u);
        cp16(sb + PL_OFF + tid * 16, wloc   + tid * 4, 16u);
        cp16(sb + PC_OFF + tid * 16, wscale + tid * 4, 16u);
    }
#pragma unroll
    for (int it = 0; it < 2; it++) {
        int idx = tid + it * 256;            // 0..511
        int r = idx >> 5;                    // 0..15
        int q8 = (idx & 31) * 8;             // 0..248
        cp16(sb + A_OFF + (uint32_t)(r * LDA_H + q8) * 2,
             g_fh + (size_t)(rowBase + r) * F_DIM + q8, 16u);
    }
    if (tid < 16) f2s[tid] = g_f2[rowBase + tid];

    // first B sub-chunk (chunk 0, k [0,32)) into buffer 0
    auto loadB = [&](int colBase, int k0, int buf) {
#pragma unroll
        for (int it = 0; it < 2; it++) {
            int idx = tid + it * 256;        // 0..511
            int col = idx >> 2;              // 0..127
            int q8 = (idx & 3) * 8;          // 0..24
            int gc = colBase + col;
            cp16(sb + B_OFF + (uint32_t)buf * 10240 + (uint32_t)(col * LDB_H + q8) * 2,
                 g_mh + (size_t)((gc < C_CLS) ? gc : 0) * F_DIM + k0 + q8,
                 (gc < C_CLS) ? 16u : 0u);
        }
    };
    loadB(0, 0, 0);
    asm volatile("cp.async.commit_group;" ::: "memory");
    asm volatile("cp.async.wait_group 0;" ::: "memory");
    __syncthreads();

    const int g = lane >> 2;       // 0..7
    const int kq = lane & 3;       // 0..3
    const int lq = lane & 3;
    const int lr = lane >> 2;
    const __half* Ab = (const __half*)(smem + A_OFF);

    int buf = 0;
#pragma unroll 1
    for (int c = 0; c < 8; c++) {
        float acc[2][4];
#pragma unroll
        for (int na = 0; na < 2; na++)
#pragma unroll
            for (int q = 0; q < 4; q++) acc[na][q] = 0.f;

#pragma unroll 1
        for (int sk = 0; sk < 8; sk++) {
            int nc = c, nsk = sk + 1;
            if (nsk == 8) { nc = c + 1; nsk = 0; }
            const bool hasNext = (nc < 8);
            if (hasNext) {
                loadB(nc * 128, nsk * 32, buf ^ 1);
                asm volatile("cp.async.commit_group;" ::: "memory");
                asm volatile("cp.async.wait_group 1;" ::: "memory");
            } else {
                asm volatile("cp.async.wait_group 0;" ::: "memory");
            }
            __syncthreads();

            const __half* Bb = (const __half*)(smem + B_OFF + buf * 10240);
#pragma unroll
            for (int ks = 0; ks < 2; ks++) {
                const int kbg = sk * 32 + ks * 16 + 2 * kq;   // A k (global)
                const int kbl = ks * 16 + 2 * kq;             // B k (local)
                uint32_t a[4], b[2][2];
                const __half* ap = Ab + g * LDA_H + kbg;
                a[0] = *(const uint32_t*)(ap);
                a[1] = *(const uint32_t*)(ap + 8 * LDA_H);
                a[2] = *(const uint32_t*)(ap + 8);
                a[3] = *(const uint32_t*)(ap + 8 * LDA_H + 8);
#pragma unroll
                for (int na = 0; na < 2; na++) {
                    const __half* bp = Bb + (wid * 16 + na * 8 + g) * LDB_H + kbl;
                    b[na][0] = *(const uint32_t*)(bp);
                    b[na][1] = *(const uint32_t*)(bp + 8);
                }
#pragma unroll
                for (int na = 0; na < 2; na++)
                    mma_f16(acc[na], a, b[na]);
            }
            __syncthreads();
            buf ^= 1;
        }

        // ---- per-chunk OpenMax epilogue -> smem scores ----
        const int colBase = c * 128;
#pragma unroll
        for (int na = 0; na < 2; na++) {
#pragma unroll
            for (int h = 0; h < 2; h++) {
                const int row = lr + 8 * h;
                const int gc = colBase + wid * 16 + na * 8 + 2 * lq;
                float2 res;
                if (gc < C_CLS) {   // gc even, C even -> pair fully valid
                    const float f2v = f2s[row];
                    float2 lg = *(const float2*)(logits +
                        (size_t)(rowBase + row) * C_CLS + gc);
                    float dots[2] = { acc[na][h * 2], acc[na][h * 2 + 1] };
                    float lgv[2] = { lg.x, lg.y };
                    float r2[2];
#pragma unroll
                    for (int q = 0; q < 2; q++) {
                        const int cc = gc + q;
                        float d2 = f2v + m2s[cc] - 2.f * dots[q];
                        float dist = sqrtf(fmaxf(d2, 1e-12f));
                        float xp = __fdividef(dist - lcs[cc], wss[cc]);
                        float wv = 0.f;
                        if (xp > 0.f) {
                            float p = exp2f(shs[cc] * __log2f(xp));
                            wv = 1.f - __expf(-p);
                        }
                        float w2 = wv * wv;
                        float w4 = w2 * w2;
                        float w10 = w4 * w4 * w2;
                        r2[q] = lgv[q] * (1.f - w10);
                    }
                    res.x = r2[0]; res.y = r2[1];
                } else {
                    res.x = -1e30f; res.y = -1e30f;
                }
                *(float2*)(scs + row * 1024 + gc) = res;
            }
        }
    }

    __syncthreads();

    // ---- in-CTA softmax: warp w handles rows 2w, 2w+1 (3-pass over smem) ----
#pragma unroll
    for (int rr = 0; rr < 2; rr++) {
        const int row = wid * 2 + rr;
        float* rp = scs + row * 1024;
        float mx = -1e30f;
#pragma unroll
        for (int j = 0; j < 32; j++) mx = fmaxf(mx, rp[lane + 32 * j]);
#pragma unroll
        for (int o = 16; o; o >>= 1) mx = fmaxf(mx, __shfl_xor_sync(0xffffffffu, mx, o));
        float s = 0.f;
#pragma unroll
        for (int j = 0; j < 32; j++) {
            float e = __expf(rp[lane + 32 * j] - mx);
            rp[lane + 32 * j] = e;
            s += e;
        }
#pragma unroll
        for (int o = 16; o; o >>= 1) s += __shfl_xor_sync(0xffffffffu, s, o);
        const float inv = 1.f / s;
        float* orow = out + (size_t)(rowBase + row) * C_CLS;
#pragma unroll
        for (int j = 0; j < 32; j++) {
            int col = lane + 32 * j;
            if (col < C_CLS) orow[col] = rp[col] * inv;
        }
    }
}

// -------------------------------------------------------------------------
extern "C" void kernel_launch(void* const* d_in, const int* in_sizes, int n_in,
                              void* d_out, int out_size) {
    const float* logits    = (const float*)d_in[0];
    const float* features  = (const float*)d_in[1];
    const float* mean_vecs = (const float*)d_in[2];
    const float* wb_shape  = (const float*)d_in[3];
    const float* wb_loc    = (const float*)d_in[4];
    const float* wb_scale  = (const float*)d_in[5];
    float* out = (float*)d_out;

    __half *fh, *mh;
    float *f2, *m2;
    cudaGetSymbolAddress((void**)&fh, g_fh);
    cudaGetSymbolAddress((void**)&mh, g_mh);
    cudaGetSymbolAddress((void**)&f2, g_f2);
    cudaGetSymbolAddress((void**)&m2, g_m2);

    cudaFuncSetAttribute(openmax_fused,
                         cudaFuncAttributeMaxDynamicSharedMemorySize, SMEM_BYTES);

    convert_kernel<<<B_ROWS / 8, 256>>>(features, fh, f2, B_ROWS);
    convert_kernel<<<(C_CLS + 7) / 8, 256>>>(mean_vecs, mh, m2, C_CLS);

    openmax_fused<<<B_ROWS / BM, 256, SMEM_BYTES>>>(logits, wb_shape, wb_loc,
                                                    wb_scale, out);
    (void)in_sizes; (void)n_in; (void)out_size;
}